// round 2
// baseline (speedup 1.0000x reference)
#include <cuda_runtime.h>

// out[m,k] = D*(w-1)*sum_j t[m,j], broadcast over k. M=16384, D=2048.
// Warp-per-row: no block barriers, deep MLP, streaming cache hints.

#define M_ROWS 16384
#define D_COLS 2048
#define NTHREADS 256
#define WARPS_PER_CTA (NTHREADS / 32)
#define VEC_PER_LANE (D_COLS / 4 / 32)   // 16 float4 per lane

__global__ __launch_bounds__(NTHREADS)
void perm_equiv_warp_kernel(const float* __restrict__ t,
                            const float* __restrict__ w,
                            float* __restrict__ out) {
    const int lane = threadIdx.x & 31;
    const int wid  = threadIdx.x >> 5;
    const int m    = blockIdx.x * WARPS_PER_CTA + wid;

    const float4* __restrict__ row =
        reinterpret_cast<const float4*>(t + (size_t)m * D_COLS) + lane;

    // 16 streaming float4 loads per lane, 4 accumulators for ILP
    float s0 = 0.f, s1 = 0.f, s2 = 0.f, s3 = 0.f;
    #pragma unroll
    for (int i = 0; i < VEC_PER_LANE; i += 4) {
        float4 a = __ldcs(row + (i + 0) * 32);
        float4 b = __ldcs(row + (i + 1) * 32);
        float4 c = __ldcs(row + (i + 2) * 32);
        float4 d = __ldcs(row + (i + 3) * 32);
        s0 += (a.x + a.y) + (a.z + a.w);
        s1 += (b.x + b.y) + (b.z + b.w);
        s2 += (c.x + c.y) + (c.z + c.w);
        s3 += (d.x + d.y) + (d.z + d.w);
    }
    float s = (s0 + s1) + (s2 + s3);

    // Butterfly reduce: every lane ends with the full row sum
    #pragma unroll
    for (int off = 16; off > 0; off >>= 1)
        s += __shfl_xor_sync(0xFFFFFFFFu, s, off);

    const float v = (float)D_COLS * (w[0] - 1.0f) * s;
    const float4 vv = make_float4(v, v, v, v);

    float4* __restrict__ orow =
        reinterpret_cast<float4*>(out + (size_t)m * D_COLS) + lane;
    #pragma unroll
    for (int i = 0; i < VEC_PER_LANE; i++)
        __stcs(orow + i * 32, vv);
}

extern "C" void kernel_launch(void* const* d_in, const int* in_sizes, int n_in,
                              void* d_out, int out_size) {
    const float* t = (const float*)d_in[0];
    const float* w = (const float*)d_in[1];
    float* out = (float*)d_out;
    perm_equiv_warp_kernel<<<M_ROWS / WARPS_PER_CTA, NTHREADS>>>(t, w, out);
}

// round 3
// speedup vs baseline: 1.0530x; 1.0530x over previous
#include <cuda_runtime.h>

// out[m,k] = D*(w-1)*sum_j t[m,j], broadcast over k. M=16384, D=2048.
// Block-per-row (MLP_p1=2, low L1tex contention), single-barrier reduction,
// streaming cache hints on both sides.

#define M_ROWS 16384
#define D_COLS 2048
#define NTHREADS 256
#define NWARPS (NTHREADS / 32)

__global__ __launch_bounds__(NTHREADS)
void perm_equiv_kernel(const float* __restrict__ t,
                       const float* __restrict__ w,
                       float* __restrict__ out) {
    const int m   = blockIdx.x;
    const int tid = threadIdx.x;
    const int lane = tid & 31;
    const int wid  = tid >> 5;

    const float4* __restrict__ row =
        reinterpret_cast<const float4*>(t + (size_t)m * D_COLS);

    // Two streaming float4 loads per thread (512 vec / 256 threads)
    float4 a = __ldcs(row + tid);
    float4 b = __ldcs(row + tid + NTHREADS);
    float s = ((a.x + a.y) + (a.z + a.w)) + ((b.x + b.y) + (b.z + b.w));

    // Butterfly: every lane holds the warp total
    #pragma unroll
    for (int off = 16; off > 0; off >>= 1)
        s += __shfl_xor_sync(0xFFFFFFFFu, s, off);

    __shared__ float warp_sums[NWARPS];
    if (lane == 0) warp_sums[wid] = s;
    __syncthreads();

    // Every thread sums the 8 warp partials itself (broadcast LDS, no 2nd barrier)
    float total = 0.f;
    #pragma unroll
    for (int i = 0; i < NWARPS; i++) total += warp_sums[i];

    const float v = (float)D_COLS * (__ldg(w) - 1.0f) * total;
    const float4 vv = make_float4(v, v, v, v);

    float4* __restrict__ orow =
        reinterpret_cast<float4*>(out + (size_t)m * D_COLS);
    __stcs(orow + tid, vv);
    __stcs(orow + tid + NTHREADS, vv);
}

extern "C" void kernel_launch(void* const* d_in, const int* in_sizes, int n_in,
                              void* d_out, int out_size) {
    const float* t = (const float*)d_in[0];
    const float* w = (const float*)d_in[1];
    float* out = (float*)d_out;
    perm_equiv_kernel<<<M_ROWS, NTHREADS>>>(t, w, out);
}